// round 4
// baseline (speedup 1.0000x reference)
#include <cuda_runtime.h>

#define T25   25
#define HID   100
#define G4    400
#define NROWS 12800           // 512*25

typedef unsigned long long u64;

__device__ float g_zx1[(size_t)NROWS * G4];   // layer1 input projection (incl b1)
__device__ float g_z2x[(size_t)NROWS * G4];   // layer2 input projection (incl b2)
__device__ float g_h1 [(size_t)NROWS * HID];  // layer1 hidden states, all t

union U4 { float4 f4; ulonglong2 u2; };
union U2 { float2 f2; u64 u; };

__device__ __forceinline__ u64 pk(float lo, float hi) {
    u64 r; asm("mov.b64 %0, {%1,%2};" : "=l"(r) : "f"(lo), "f"(hi)); return r;
}
__device__ __forceinline__ void ffma2(u64& d, u64 a, u64 b) {
    asm("fma.rn.f32x2 %0, %1, %2, %0;" : "+l"(d) : "l"(a), "l"(b));
}
__device__ __forceinline__ float hsum(u64 v) {
    float a, b; asm("mov.b64 {%0,%1}, %2;" : "=f"(a), "=f"(b) : "l"(v)); return a + b;
}
__device__ __forceinline__ float sigm(float x)   { return 1.0f / (1.0f + __expf(-x)); }
__device__ __forceinline__ float mytanh(float x) { float e = __expf(-2.0f * x); return (1.0f - e) / (1.0f + e); }

// ---------------------------------------------------------------------------
// Input-projection GEMM: out[row][c] = bias[c] + sum_k src(row)[k] * W[k][c]
// block = 100 rows x 400 cols; 128 blocks, 800 threads.
// W staged in smem (LDS stride-1, kills LDG latency exposure); x transposed
// in smem for row-pair FFMA2.
// ---------------------------------------------------------------------------
#define IP_SMEM_B ((HID * G4 + HID * 104) * 4)   // 201600 bytes

template<int NQ>
__device__ __forceinline__ void inproj_main(
    const float (*xs)[104], const float* __restrict__ wsm,
    int c, int rb, float bv, float* __restrict__ out, int row0)
{
    u64 acc[2 * NQ];
    u64 binit = pk(bv, bv);
    #pragma unroll
    for (int p = 0; p < 2 * NQ; p++) acc[p] = binit;

    #pragma unroll 2
    for (int k = 0; k < HID; k++) {
        float w = wsm[k * G4 + c];
        u64 wd = pk(w, w);
        const float* xr = &xs[k][rb];
        #pragma unroll
        for (int q = 0; q < NQ; q++) {
            U4 x; x.f4 = *(const float4*)(xr + 4 * q);
            ffma2(acc[2 * q],     x.u2.x, wd);
            ffma2(acc[2 * q + 1], x.u2.y, wd);
        }
    }
    #pragma unroll
    for (int p = 0; p < 2 * NQ; p++) {
        U2 v; v.u = acc[p];
        out[(long long)(row0 + rb + 2 * p) * G4 + c]     = v.f2.x;
        out[(long long)(row0 + rb + 2 * p + 1) * G4 + c] = v.f2.y;
    }
}

__global__ void __launch_bounds__(800, 1) inproj_kernel(
    const float* __restrict__ src,    // [12800][100] or null (then gather emb)
    const int*   __restrict__ feats,  // [12800] or null
    const float* __restrict__ emb,    // [VOCAB][100]
    const float* __restrict__ W,      // [100][400]
    const float* __restrict__ bias,   // [400]
    float*       __restrict__ out)    // [12800][400]
{
    extern __shared__ __align__(16) float smp[];
    float* wsm = smp;                              // [100*400]
    float (*xs)[104] = (float(*)[104])(smp + HID * G4);

    const int tid  = threadIdx.x;
    const int row0 = blockIdx.x * 100;

    // stage W (row-major copy, float4)
    for (int i4 = tid; i4 < HID * G4 / 4; i4 += 800)
        ((float4*)wsm)[i4] = ((const float4*)W)[i4];

    // stage x transposed: [k][row]
    for (int idx = tid; idx < 25 * 100; idx += 800) {
        int j4 = idx / 100, rl = idx % 100;
        const float* base = feats
            ? emb + (long long)__ldg(feats + row0 + rl) * HID
            : src + (long long)(row0 + rl) * HID;
        float4 v = *(const float4*)(base + 4 * j4);
        xs[4 * j4 + 0][rl] = v.x;
        xs[4 * j4 + 1][rl] = v.y;
        xs[4 * j4 + 2][rl] = v.z;
        xs[4 * j4 + 3][rl] = v.w;
    }
    __syncthreads();

    const int c  = tid % G4;
    const int rg = tid / G4;
    const float bv = bias[c];
    if (rg == 0) inproj_main<13>(xs, wsm, c, 0,  bv, out, row0);
    else         inproj_main<12>(xs, wsm, c, 52, bv, out, row0);
}

// ---------------------------------------------------------------------------
// Recurrence kernel, software-pipelined: two row-groups (rows {0,1},{2,3})
// staggered by half a step. Each phase = GEMM(group gg, 2 rows) overlapped
// with gates(group og), ONE barrier per phase, 51 phases.
// Recurrent weights in registers, split-k across two 400-thread halves.
// ---------------------------------------------------------------------------
__global__ void __launch_bounds__(800, 1) rec_kernel(
    const float* __restrict__ zin,    // [12800][400]
    const float* __restrict__ Wh,     // [100][400]
    float*       __restrict__ h_out,  // [12800][100] or null
    const float* __restrict__ wfc1, const float* __restrict__ bfc1,
    const float* __restrict__ wfc2, const float* __restrict__ bfc2,
    float*       __restrict__ out)    // [512][2] or null
{
    __shared__ __align__(16) float hs[4][104];      // rows 0-3, zero-padded k
    __shared__ float zp[2][2][2][G4];               // [group][khalf][rowloc][col]
    __shared__ float fc1s[4][128];

    const int tid = threadIdx.x;
    const int b0  = blockIdx.x * 4;
    const int c   = tid % G4;
    const int kh  = tid / G4;                        // k half: 0 or 1

    // preload my 52 weights (k in [kh*52, kh*52+52), zeros beyond k=99)
    u64 wp[26];
    #pragma unroll
    for (int j = 0; j < 26; j++) {
        int k = kh * 52 + 2 * j;
        float w0 = (k     < HID) ? __ldg(Wh + (k    ) * G4 + c) : 0.f;
        float w1 = (k + 1 < HID) ? __ldg(Wh + (k + 1) * G4 + c) : 0.f;
        wp[j] = pk(w0, w1);
    }
    for (int i = tid; i < 4 * 104; i += 800) ((float*)hs)[i] = 0.f;
    __syncthreads();

    const int gr = tid / 100;    // row-in-group (valid for tid < 200)
    const int gu = tid % 100;
    float cs0 = 0.f, cs1 = 0.f;              // cell state per group
    float zx0 = 0.f, zx1 = 0.f, zx2 = 0.f, zx3 = 0.f;  // zin prefetch

    #pragma unroll 2
    for (int p = 0; p <= 50; p++) {
        const int gg = p & 1;          // GEMM group this phase
        const int og = gg ^ 1;         // gate group this phase
        const int tG = p >> 1;         // GEMM time
        const int tE = (p - 1) >> 1;   // gate time

        // -- prefetch zin for next phase's gates (group gg, time tG) --
        float nz0 = 0.f, nz1 = 0.f, nz2 = 0.f, nz3 = 0.f;
        if (tG < T25 && tid < 200) {
            const float* zr = zin + ((long long)(b0 + 2 * gg + gr) * T25 + tG) * G4 + gu;
            nz0 = __ldg(zr);
            nz1 = __ldg(zr + 100);
            nz2 = __ldg(zr + 200);
            nz3 = __ldg(zr + 300);
        }

        // -- GEMM partials for group gg, rows 2gg, 2gg+1, over my k half --
        if (tG < T25) {
            u64 a0 = 0ULL, a1 = 0ULL;
            const int kb = kh * 52;
            const float* hr0 = &hs[2 * gg][kb];
            const float* hr1 = &hs[2 * gg + 1][kb];
            #pragma unroll
            for (int j4 = 0; j4 < 13; j4++) {
                U4 v0; v0.f4 = *(const float4*)(hr0 + 4 * j4);
                U4 v1; v1.f4 = *(const float4*)(hr1 + 4 * j4);
                ffma2(a0, v0.u2.x, wp[2 * j4]);
                ffma2(a0, v0.u2.y, wp[2 * j4 + 1]);
                ffma2(a1, v1.u2.x, wp[2 * j4]);
                ffma2(a1, v1.u2.y, wp[2 * j4 + 1]);
            }
            zp[gg][kh][0][c] = hsum(a0);
            zp[gg][kh][1][c] = hsum(a1);
        }

        // -- gates for group og at time tE (independent of GEMM above) --
        if (tE >= 0 && tid < 200) {
            float zi = zx0 + zp[og][0][gr][gu]       + zp[og][1][gr][gu];
            float zj = zx1 + zp[og][0][gr][gu + 100] + zp[og][1][gr][gu + 100];
            float zf = zx2 + zp[og][0][gr][gu + 200] + zp[og][1][gr][gu + 200];
            float zo = zx3 + zp[og][0][gr][gu + 300] + zp[og][1][gr][gu + 300];
            float cv = og ? cs1 : cs0;
            cv = cv * sigm(zf + 1.0f) + sigm(zi) * mytanh(zj);
            float hn = mytanh(cv) * sigm(zo);
            if (og) cs1 = cv; else cs0 = cv;
            hs[2 * og + gr][gu] = hn;
            if (h_out)
                h_out[((long long)(b0 + 2 * og + gr) * T25 + tE) * HID + gu] = hn;
        }

        zx0 = nz0; zx1 = nz1; zx2 = nz2; zx3 = nz3;
        __syncthreads();
    }

    // ---- FC head (layer-2 kernel only) ----
    if (out) {
        if (tid < 512) {
            int r = tid / 128, j = tid % 128;
            float a = bfc1[j];
            #pragma unroll 4
            for (int k = 0; k < HID; k++)
                a += hs[r][k] * __ldg(wfc1 + k * 128 + j);
            fc1s[r][j] = a;
        }
        __syncthreads();
        if (tid < 8) {
            int r = tid / 2, cc = tid % 2;
            float a = bfc2[cc];
            #pragma unroll 8
            for (int k = 0; k < 128; k++)
                a += fc1s[r][k] * __ldg(wfc2 + k * 2 + cc);
            out[(b0 + r) * 2 + cc] = a;
        }
    }
}

// ---------------------------------------------------------------------------
extern "C" void kernel_launch(void* const* d_in, const int* in_sizes, int n_in,
                              void* d_out, int out_size)
{
    const int*   feats = (const int*)  d_in[0];
    const float* emb   = (const float*)d_in[1];
    const float* k1    = (const float*)d_in[2];
    const float* b1    = (const float*)d_in[3];
    const float* k2    = (const float*)d_in[4];
    const float* b2    = (const float*)d_in[5];
    const float* wfc1  = (const float*)d_in[6];
    const float* bfc1  = (const float*)d_in[7];
    const float* wfc2  = (const float*)d_in[8];
    const float* bfc2  = (const float*)d_in[9];
    float* out = (float*)d_out;

    float *zx1, *z2x, *h1;
    cudaGetSymbolAddress((void**)&zx1, g_zx1);
    cudaGetSymbolAddress((void**)&z2x, g_z2x);
    cudaGetSymbolAddress((void**)&h1,  g_h1);

    cudaFuncSetAttribute(inproj_kernel,
                         cudaFuncAttributeMaxDynamicSharedMemorySize, IP_SMEM_B);

    // A: zx1 = emb[feats] @ k1[0:100] + b1
    inproj_kernel<<<128, 800, IP_SMEM_B>>>(nullptr, feats, emb, k1, b1, zx1);
    // B: layer-1 recurrence -> h1 (all timesteps)
    rec_kernel<<<128, 800>>>(zx1, k1 + HID * G4, h1,
                             nullptr, nullptr, nullptr, nullptr, nullptr);
    // C: z2x = h1 @ k2[0:100] + b2
    inproj_kernel<<<128, 800, IP_SMEM_B>>>(h1, nullptr, nullptr, k2, b2, z2x);
    // D: layer-2 recurrence + FC head -> out
    rec_kernel<<<128, 800>>>(z2x, k2 + HID * G4, nullptr,
                             wfc1, bfc1, wfc2, bfc2, out);
}

// round 5
// speedup vs baseline: 1.0322x; 1.0322x over previous
#include <cuda_runtime.h>

#define T25   25
#define HID   100
#define G4    400
#define NROWS 12800           // 512*25

typedef unsigned long long u64;

__device__ float g_zx1[(size_t)NROWS * G4];   // layer1 input projection (incl b1)
__device__ float g_z2x[(size_t)NROWS * G4];   // layer2 input projection (incl b2)
__device__ float g_h1 [(size_t)NROWS * HID];  // layer1 hidden states, all t

union U4 { float4 f4; ulonglong2 u2; };
union U2 { float2 f2; u64 u; };

__device__ __forceinline__ u64 pk(float lo, float hi) {
    u64 r; asm("mov.b64 %0, {%1,%2};" : "=l"(r) : "f"(lo), "f"(hi)); return r;
}
__device__ __forceinline__ void ffma2(u64& d, u64 a, u64 b) {
    asm("fma.rn.f32x2 %0, %1, %2, %0;" : "+l"(d) : "l"(a), "l"(b));
}
__device__ __forceinline__ float hsum(u64 v) {
    float a, b; asm("mov.b64 {%0,%1}, %2;" : "=f"(a), "=f"(b) : "l"(v)); return a + b;
}
__device__ __forceinline__ float sigm(float x)   { return 1.0f / (1.0f + __expf(-x)); }
__device__ __forceinline__ float mytanh(float x) { float e = __expf(-2.0f * x); return (1.0f - e) / (1.0f + e); }

// ---------------------------------------------------------------------------
// Input-projection GEMM: out[row][c] = bias[c] + sum_k src(row)[k] * W[k][c]
// block = 100 rows x 400 cols; 128 blocks, 800 threads. W staged in smem.
// ---------------------------------------------------------------------------
#define IP_SMEM_B ((HID * G4 + HID * 104) * 4)   // 201600 bytes

template<int NQ>
__device__ __forceinline__ void inproj_main(
    const float (*xs)[104], const float* __restrict__ wsm,
    int c, int rb, float bv, float* __restrict__ out, int row0)
{
    u64 acc[2 * NQ];
    u64 binit = pk(bv, bv);
    #pragma unroll
    for (int p = 0; p < 2 * NQ; p++) acc[p] = binit;

    #pragma unroll 2
    for (int k = 0; k < HID; k++) {
        float w = wsm[k * G4 + c];
        u64 wd = pk(w, w);
        const float* xr = &xs[k][rb];
        #pragma unroll
        for (int q = 0; q < NQ; q++) {
            U4 x; x.f4 = *(const float4*)(xr + 4 * q);
            ffma2(acc[2 * q],     x.u2.x, wd);
            ffma2(acc[2 * q + 1], x.u2.y, wd);
        }
    }
    #pragma unroll
    for (int p = 0; p < 2 * NQ; p++) {
        U2 v; v.u = acc[p];
        out[(long long)(row0 + rb + 2 * p) * G4 + c]     = v.f2.x;
        out[(long long)(row0 + rb + 2 * p + 1) * G4 + c] = v.f2.y;
    }
}

__global__ void __launch_bounds__(800, 1) inproj_kernel(
    const float* __restrict__ src,    // [12800][100] or null (then gather emb)
    const int*   __restrict__ feats,  // [12800] or null
    const float* __restrict__ emb,    // [VOCAB][100]
    const float* __restrict__ W,      // [100][400]
    const float* __restrict__ bias,   // [400]
    float*       __restrict__ out)    // [12800][400]
{
    extern __shared__ __align__(16) float smp[];
    float* wsm = smp;                              // [100*400]
    float (*xs)[104] = (float(*)[104])(smp + HID * G4);

    const int tid  = threadIdx.x;
    const int row0 = blockIdx.x * 100;

    for (int i4 = tid; i4 < HID * G4 / 4; i4 += 800)
        ((float4*)wsm)[i4] = ((const float4*)W)[i4];

    for (int idx = tid; idx < 25 * 100; idx += 800) {
        int j4 = idx / 100, rl = idx % 100;
        const float* base = feats
            ? emb + (long long)__ldg(feats + row0 + rl) * HID
            : src + (long long)(row0 + rl) * HID;
        float4 v = *(const float4*)(base + 4 * j4);
        xs[4 * j4 + 0][rl] = v.x;
        xs[4 * j4 + 1][rl] = v.y;
        xs[4 * j4 + 2][rl] = v.z;
        xs[4 * j4 + 3][rl] = v.w;
    }
    __syncthreads();

    const int c  = tid % G4;
    const int rg = tid / G4;
    const float bv = bias[c];
    if (rg == 0) inproj_main<13>(xs, wsm, c, 0,  bv, out, row0);
    else         inproj_main<12>(xs, wsm, c, 52, bv, out, row0);
}

// ---------------------------------------------------------------------------
// Recurrence kernel (R3 structure + cross-step zin prefetch carried in regs,
// zin folded into GEMM accumulator init -> shorter serial gate phase).
// Block = 4 batch rows, 800 threads = 400 cols x 2 k-halves, weights in regs.
// ---------------------------------------------------------------------------
__global__ void __launch_bounds__(800, 1) rec_kernel(
    const float* __restrict__ zin,    // [12800][400]
    const float* __restrict__ Wh,     // [100][400]
    float*       __restrict__ h_out,  // [12800][100] or null
    const float* __restrict__ wfc1, const float* __restrict__ bfc1,
    const float* __restrict__ wfc2, const float* __restrict__ bfc2,
    float*       __restrict__ out)    // [512][2] or null
{
    __shared__ __align__(16) float hs[4][104];      // rows 0-3, zero-padded k
    __shared__ float zp[2][4][G4];                  // [khalf][row][col]
    __shared__ float fc1s[4][128];

    const int tid = threadIdx.x;
    const int b0  = blockIdx.x * 4;
    const int c   = tid % G4;
    const int kh  = tid / G4;                        // k half: 0 or 1

    // preload my 52 weights (k in [kh*52, kh*52+52), zeros beyond k=99)
    u64 wp[26];
    #pragma unroll
    for (int j = 0; j < 26; j++) {
        int k = kh * 52 + 2 * j;
        float w0 = (k     < HID) ? __ldg(Wh + (k    ) * G4 + c) : 0.f;
        float w1 = (k + 1 < HID) ? __ldg(Wh + (k + 1) * G4 + c) : 0.f;
        wp[j] = pk(w0, w1);
    }
    for (int i = tid; i < 4 * 104; i += 800) ((float*)hs)[i] = 0.f;
    __syncthreads();

    const int gr = tid / 100;    // gate row (valid for tid < 400)
    const int gu = tid % 100;
    float cst = 0.f;

    // zin rows owned by this thread for accumulator init: rows 2kh, 2kh+1
    const float* zr0 = zin + ((long long)(b0 + 2 * kh    ) * T25) * G4 + c;
    const float* zr1 = zin + ((long long)(b0 + 2 * kh + 1) * T25) * G4 + c;
    float za = __ldg(zr0);        // t = 0 prefetch
    float zb = __ldg(zr1);

    for (int t = 0; t < T25; t++) {
        // ---- GEMM over my k half; zin folded into acc init ----
        u64 acc[4];
        acc[2 * kh]     = pk(za, 0.f);
        acc[2 * kh + 1] = pk(zb, 0.f);
        acc[2 * (kh ^ 1)]     = 0ULL;
        acc[2 * (kh ^ 1) + 1] = 0ULL;

        const int kb = kh * 52;
        #pragma unroll
        for (int j4 = 0; j4 < 13; j4++) {
            #pragma unroll
            for (int r = 0; r < 4; r++) {
                U4 hv; hv.f4 = *(const float4*)&hs[r][kb + 4 * j4];
                ffma2(acc[r], hv.u2.x, wp[2 * j4]);
                ffma2(acc[r], hv.u2.y, wp[2 * j4 + 1]);
            }
        }

        // prefetch zin for step t+1 (consumed after two barriers)
        if (t + 1 < T25) {
            za = __ldg(zr0 + (t + 1) * G4);
            zb = __ldg(zr1 + (t + 1) * G4);
        }

        zp[kh][0][c] = hsum(acc[0]);
        zp[kh][1][c] = hsum(acc[1]);
        zp[kh][2][c] = hsum(acc[2]);
        zp[kh][3][c] = hsum(acc[3]);
        __syncthreads();

        // ---- gates (tid < 400); z already includes zin ----
        if (tid < 400) {
            float zi = zp[0][gr][gu]       + zp[1][gr][gu];
            float zj = zp[0][gr][gu + 100] + zp[1][gr][gu + 100];
            float zf = zp[0][gr][gu + 200] + zp[1][gr][gu + 200];
            float zo = zp[0][gr][gu + 300] + zp[1][gr][gu + 300];
            cst = cst * sigm(zf + 1.0f) + sigm(zi) * mytanh(zj);
            float hn = mytanh(cst) * sigm(zo);
            hs[gr][gu] = hn;
            if (h_out)
                h_out[((long long)(b0 + gr) * T25 + t) * HID + gu] = hn;
        }
        __syncthreads();
    }

    // ---- FC head (layer-2 kernel only) ----
    if (out) {
        if (tid < 512) {
            int r = tid / 128, j = tid % 128;
            float a = bfc1[j];
            #pragma unroll 4
            for (int k = 0; k < HID; k++)
                a += hs[r][k] * __ldg(wfc1 + k * 128 + j);
            fc1s[r][j] = a;
        }
        __syncthreads();
        if (tid < 8) {
            int r = tid / 2, cc = tid % 2;
            float a = bfc2[cc];
            #pragma unroll 8
            for (int k = 0; k < 128; k++)
                a += fc1s[r][k] * __ldg(wfc2 + k * 2 + cc);
            out[(b0 + r) * 2 + cc] = a;
        }
    }
}

// ---------------------------------------------------------------------------
extern "C" void kernel_launch(void* const* d_in, const int* in_sizes, int n_in,
                              void* d_out, int out_size)
{
    const int*   feats = (const int*)  d_in[0];
    const float* emb   = (const float*)d_in[1];
    const float* k1    = (const float*)d_in[2];
    const float* b1    = (const float*)d_in[3];
    const float* k2    = (const float*)d_in[4];
    const float* b2    = (const float*)d_in[5];
    const float* wfc1  = (const float*)d_in[6];
    const float* bfc1  = (const float*)d_in[7];
    const float* wfc2  = (const float*)d_in[8];
    const float* bfc2  = (const float*)d_in[9];
    float* out = (float*)d_out;

    float *zx1, *z2x, *h1;
    cudaGetSymbolAddress((void**)&zx1, g_zx1);
    cudaGetSymbolAddress((void**)&z2x, g_z2x);
    cudaGetSymbolAddress((void**)&h1,  g_h1);

    cudaFuncSetAttribute(inproj_kernel,
                         cudaFuncAttributeMaxDynamicSharedMemorySize, IP_SMEM_B);

    // A: zx1 = emb[feats] @ k1[0:100] + b1
    inproj_kernel<<<128, 800, IP_SMEM_B>>>(nullptr, feats, emb, k1, b1, zx1);
    // B: layer-1 recurrence -> h1 (all timesteps)
    rec_kernel<<<128, 800>>>(zx1, k1 + HID * G4, h1,
                             nullptr, nullptr, nullptr, nullptr, nullptr);
    // C: z2x = h1 @ k2[0:100] + b2
    inproj_kernel<<<128, 800, IP_SMEM_B>>>(h1, nullptr, nullptr, k2, b2, z2x);
    // D: layer-2 recurrence + FC head -> out
    rec_kernel<<<128, 800>>>(z2x, k2 + HID * G4, nullptr,
                             wfc1, bfc1, wfc2, bfc2, out);
}

// round 6
// speedup vs baseline: 1.2993x; 1.2587x over previous
#include <cuda_runtime.h>

#define T25   25
#define HID   100
#define G4    400
#define NROWS 12800           // 512*25

typedef unsigned long long u64;

__device__ float g_zx1[(size_t)NROWS * G4];   // layer1 input projection (incl b1)
__device__ float g_z2x[(size_t)NROWS * G4];   // layer2 input projection (incl b2)
__device__ float g_h1 [(size_t)NROWS * HID];  // layer1 hidden states, all t

union U4 { float4 f4; ulonglong2 u2; };
union U2 { float2 f2; u64 u; };

__device__ __forceinline__ u64 pk(float lo, float hi) {
    u64 r; asm("mov.b64 %0, {%1,%2};" : "=l"(r) : "f"(lo), "f"(hi)); return r;
}
__device__ __forceinline__ void ffma2(u64& d, u64 a, u64 b) {
    asm("fma.rn.f32x2 %0, %1, %2, %0;" : "+l"(d) : "l"(a), "l"(b));
}
__device__ __forceinline__ float hsum(u64 v) {
    float a, b; asm("mov.b64 {%0,%1}, %2;" : "=f"(a), "=f"(b) : "l"(v)); return a + b;
}
__device__ __forceinline__ float sigm(float x)   { return 1.0f / (1.0f + __expf(-x)); }
__device__ __forceinline__ float mytanh(float x) { float e = __expf(-2.0f * x); return (1.0f - e) / (1.0f + e); }

// ---------------------------------------------------------------------------
// Input-projection GEMM: out[row][c] = bias[c] + sum_k src(row)[k] * W[k][c]
// block = 100 rows x 400 cols; 128 blocks, 800 threads. W staged in smem.
// ---------------------------------------------------------------------------
#define IP_SMEM_B ((HID * G4 + HID * 104) * 4)   // 201600 bytes

template<int NQ>
__device__ __forceinline__ void inproj_main(
    const float (*xs)[104], const float* __restrict__ wsm,
    int c, int rb, float bv, float* __restrict__ out, int row0)
{
    u64 acc[2 * NQ];
    u64 binit = pk(bv, bv);
    #pragma unroll
    for (int p = 0; p < 2 * NQ; p++) acc[p] = binit;

    #pragma unroll 2
    for (int k = 0; k < HID; k++) {
        float w = wsm[k * G4 + c];
        u64 wd = pk(w, w);
        const float* xr = &xs[k][rb];
        #pragma unroll
        for (int q = 0; q < NQ; q++) {
            U4 x; x.f4 = *(const float4*)(xr + 4 * q);
            ffma2(acc[2 * q],     x.u2.x, wd);
            ffma2(acc[2 * q + 1], x.u2.y, wd);
        }
    }
    #pragma unroll
    for (int p = 0; p < 2 * NQ; p++) {
        U2 v; v.u = acc[p];
        out[(long long)(row0 + rb + 2 * p) * G4 + c]     = v.f2.x;
        out[(long long)(row0 + rb + 2 * p + 1) * G4 + c] = v.f2.y;
    }
}

__global__ void __launch_bounds__(800, 1) inproj_kernel(
    const float* __restrict__ src,    // [12800][100] or null (then gather emb)
    const int*   __restrict__ feats,  // [12800] or null
    const float* __restrict__ emb,    // [VOCAB][100]
    const float* __restrict__ W,      // [100][400]
    const float* __restrict__ bias,   // [400]
    float*       __restrict__ out)    // [12800][400]
{
    extern __shared__ __align__(16) float smp[];
    float* wsm = smp;                              // [100*400]
    float (*xs)[104] = (float(*)[104])(smp + HID * G4);

    const int tid  = threadIdx.x;
    const int row0 = blockIdx.x * 100;

    for (int i4 = tid; i4 < HID * G4 / 4; i4 += 800)
        ((float4*)wsm)[i4] = ((const float4*)W)[i4];

    for (int idx = tid; idx < 25 * 100; idx += 800) {
        int j4 = idx / 100, rl = idx % 100;
        const float* base = feats
            ? emb + (long long)__ldg(feats + row0 + rl) * HID
            : src + (long long)(row0 + rl) * HID;
        float4 v = *(const float4*)(base + 4 * j4);
        xs[4 * j4 + 0][rl] = v.x;
        xs[4 * j4 + 1][rl] = v.y;
        xs[4 * j4 + 2][rl] = v.z;
        xs[4 * j4 + 3][rl] = v.w;
    }
    __syncthreads();

    const int c  = tid % G4;
    const int rg = tid / G4;
    const float bv = bias[c];
    if (rg == 0) inproj_main<13>(xs, wsm, c, 0,  bv, out, row0);
    else         inproj_main<12>(xs, wsm, c, 52, bv, out, row0);
}

// ---------------------------------------------------------------------------
// Recurrence kernel. R3 structure; zin folded into accumulator init with
// COMPILE-TIME indexing (named scalars, branch on kh once) and cross-step
// prefetch issued before the GEMM loop. Weights in regs, split-k halves.
// ---------------------------------------------------------------------------
__global__ void __launch_bounds__(800, 1) rec_kernel(
    const float* __restrict__ zin,    // [12800][400]
    const float* __restrict__ Wh,     // [100][400]
    float*       __restrict__ h_out,  // [12800][100] or null
    const float* __restrict__ wfc1, const float* __restrict__ bfc1,
    const float* __restrict__ wfc2, const float* __restrict__ bfc2,
    float*       __restrict__ out)    // [512][2] or null
{
    __shared__ __align__(16) float hs[4][104];      // rows 0-3, zero-padded k
    __shared__ float zp[2][4][G4];                  // [khalf][row][col]
    __shared__ float fc1s[4][128];

    const int tid = threadIdx.x;
    const int b0  = blockIdx.x * 4;
    const int c   = tid % G4;
    const int kh  = tid / G4;                        // k half: 0 or 1

    // preload my 52 weights (k in [kh*52, kh*52+52), zeros beyond k=99)
    u64 wp[26];
    #pragma unroll
    for (int j = 0; j < 26; j++) {
        int k = kh * 52 + 2 * j;
        float w0 = (k     < HID) ? __ldg(Wh + (k    ) * G4 + c) : 0.f;
        float w1 = (k + 1 < HID) ? __ldg(Wh + (k + 1) * G4 + c) : 0.f;
        wp[j] = pk(w0, w1);
    }
    for (int i = tid; i < 4 * 104; i += 800) ((float*)hs)[i] = 0.f;
    __syncthreads();

    const int gr = tid / 100;    // gate row (valid for tid < 400)
    const int gu = tid % 100;
    float cst = 0.f;

    // zin rows owned for accumulator init: rows 2kh, 2kh+1 of this block
    const float* zr0 = zin + ((long long)(b0 + 2 * kh    ) * T25) * G4 + c;
    const float* zr1 = zin + ((long long)(b0 + 2 * kh + 1) * T25) * G4 + c;
    float za = __ldg(zr0);        // t = 0 prefetch
    float zb = __ldg(zr1);

    for (int t = 0; t < T25; t++) {
        // ---- acc init: fold zin (compile-time indexed; no spills) ----
        u64 a0, a1, a2, a3;
        if (kh == 0) { a0 = pk(za, 0.f); a1 = pk(zb, 0.f); a2 = 0ULL; a3 = 0ULL; }
        else         { a0 = 0ULL; a1 = 0ULL; a2 = pk(za, 0.f); a3 = pk(zb, 0.f); }

        // prefetch zin for step t+1 (consumed after two barriers)
        if (t + 1 < T25) {
            za = __ldg(zr0 + (t + 1) * G4);
            zb = __ldg(zr1 + (t + 1) * G4);
        }

        // ---- GEMM over my k half ----
        const int kb = kh * 52;
        #pragma unroll
        for (int j4 = 0; j4 < 13; j4++) {
            U4 v0; v0.f4 = *(const float4*)&hs[0][kb + 4 * j4];
            U4 v1; v1.f4 = *(const float4*)&hs[1][kb + 4 * j4];
            U4 v2; v2.f4 = *(const float4*)&hs[2][kb + 4 * j4];
            U4 v3; v3.f4 = *(const float4*)&hs[3][kb + 4 * j4];
            ffma2(a0, v0.u2.x, wp[2 * j4]);
            ffma2(a0, v0.u2.y, wp[2 * j4 + 1]);
            ffma2(a1, v1.u2.x, wp[2 * j4]);
            ffma2(a1, v1.u2.y, wp[2 * j4 + 1]);
            ffma2(a2, v2.u2.x, wp[2 * j4]);
            ffma2(a2, v2.u2.y, wp[2 * j4 + 1]);
            ffma2(a3, v3.u2.x, wp[2 * j4]);
            ffma2(a3, v3.u2.y, wp[2 * j4 + 1]);
        }

        zp[kh][0][c] = hsum(a0);
        zp[kh][1][c] = hsum(a1);
        zp[kh][2][c] = hsum(a2);
        zp[kh][3][c] = hsum(a3);
        __syncthreads();

        // ---- gates (tid < 400); z already includes zin + bias ----
        if (tid < 400) {
            float zi = zp[0][gr][gu]       + zp[1][gr][gu];
            float zj = zp[0][gr][gu + 100] + zp[1][gr][gu + 100];
            float zf = zp[0][gr][gu + 200] + zp[1][gr][gu + 200];
            float zo = zp[0][gr][gu + 300] + zp[1][gr][gu + 300];
            cst = cst * sigm(zf + 1.0f) + sigm(zi) * mytanh(zj);
            float hn = mytanh(cst) * sigm(zo);
            hs[gr][gu] = hn;
            if (h_out)
                h_out[((long long)(b0 + gr) * T25 + t) * HID + gu] = hn;
        }
        __syncthreads();
    }

    // ---- FC head (layer-2 kernel only) ----
    if (out) {
        if (tid < 512) {
            int r = tid / 128, j = tid % 128;
            float a = bfc1[j];
            #pragma unroll 4
            for (int k = 0; k < HID; k++)
                a += hs[r][k] * __ldg(wfc1 + k * 128 + j);
            fc1s[r][j] = a;
        }
        __syncthreads();
        if (tid < 8) {
            int r = tid / 2, cc = tid % 2;
            float a = bfc2[cc];
            #pragma unroll 8
            for (int k = 0; k < 128; k++)
                a += fc1s[r][k] * __ldg(wfc2 + k * 2 + cc);
            out[(b0 + r) * 2 + cc] = a;
        }
    }
}

// ---------------------------------------------------------------------------
extern "C" void kernel_launch(void* const* d_in, const int* in_sizes, int n_in,
                              void* d_out, int out_size)
{
    const int*   feats = (const int*)  d_in[0];
    const float* emb   = (const float*)d_in[1];
    const float* k1    = (const float*)d_in[2];
    const float* b1    = (const float*)d_in[3];
    const float* k2    = (const float*)d_in[4];
    const float* b2    = (const float*)d_in[5];
    const float* wfc1  = (const float*)d_in[6];
    const float* bfc1  = (const float*)d_in[7];
    const float* wfc2  = (const float*)d_in[8];
    const float* bfc2  = (const float*)d_in[9];
    float* out = (float*)d_out;

    float *zx1, *z2x, *h1;
    cudaGetSymbolAddress((void**)&zx1, g_zx1);
    cudaGetSymbolAddress((void**)&z2x, g_z2x);
    cudaGetSymbolAddress((void**)&h1,  g_h1);

    cudaFuncSetAttribute(inproj_kernel,
                         cudaFuncAttributeMaxDynamicSharedMemorySize, IP_SMEM_B);

    // A: zx1 = emb[feats] @ k1[0:100] + b1
    inproj_kernel<<<128, 800, IP_SMEM_B>>>(nullptr, feats, emb, k1, b1, zx1);
    // B: layer-1 recurrence -> h1 (all timesteps)
    rec_kernel<<<128, 800>>>(zx1, k1 + HID * G4, h1,
                             nullptr, nullptr, nullptr, nullptr, nullptr);
    // C: z2x = h1 @ k2[0:100] + b2
    inproj_kernel<<<128, 800, IP_SMEM_B>>>(h1, nullptr, nullptr, k2, b2, z2x);
    // D: layer-2 recurrence + FC head -> out
    rec_kernel<<<128, 800>>>(z2x, k2 + HID * G4, nullptr,
                             wfc1, bfc1, wfc2, bfc2, out);
}